// round 11
// baseline (speedup 1.0000x reference)
#include <cuda_runtime.h>
#include <cuda_bf16.h>

#define BB 8
#define SS 1024
#define HH 8
#define EE 64
#define NBH (BB*HH)
#define NTOK (BB*SS)

typedef unsigned long long u64;
typedef unsigned int u32;

__device__ __align__(16) float g_attn[NTOK * EE];   // 2 MB scratch

// ---------------------------------------------------------------------------
// helpers
// ---------------------------------------------------------------------------
__device__ __forceinline__ u64 pk2(float lo, float hi) {
    u64 r; asm("mov.b64 %0, {%1, %2};" : "=l"(r) : "f"(lo), "f"(hi)); return r;
}
__device__ __forceinline__ u64 pfma(u64 a, u64 b, u64 c) {
    u64 d; asm("fma.rn.f32x2 %0, %1, %2, %3;" : "=l"(d) : "l"(a), "l"(b), "l"(c)); return d;
}
__device__ __forceinline__ float ex2(float x) {
    float y; asm("ex2.approx.f32 %0, %1;" : "=f"(y) : "f"(x)); return y;
}
// pack two fp32 -> bf16x2; first arg lands in HIGH half, second in LOW half
__device__ __forceinline__ u32 cvtpk(float hi, float lo) {
    u32 r; asm("cvt.rn.bf16x2.f32 %0, %1, %2;" : "=r"(r) : "f"(hi), "f"(lo)); return r;
}
// bf16x2 halves back to fp32 (bf16->f32 is a 16-bit shift)
__device__ __forceinline__ float bflo_f(u32 w) { return __uint_as_float(w << 16); }
__device__ __forceinline__ float bfhi_f(u32 w) { return __uint_as_float(w & 0xffff0000u); }
__device__ __forceinline__ float bfrnd(float v) {
    return __bfloat162float(__float2bfloat16(v));
}

// m16n8k16 row.col bf16 MMA, fp32 accum (HMMA fallback path, sm_80+ PTX)
#define MMA_BF16(d0,d1,d2,d3, a0,a1,a2,a3, b0,b1, c0,c1,c2,c3) \
  asm volatile("mma.sync.aligned.m16n8k16.row.col.f32.bf16.bf16.f32 " \
    "{%0,%1,%2,%3}, {%4,%5,%6,%7}, {%8,%9}, {%10,%11,%12,%13};" \
    : "=f"(d0),"=f"(d1),"=f"(d2),"=f"(d3) \
    : "r"(a0),"r"(a1),"r"(a2),"r"(a3), "r"(b0),"r"(b1), \
      "f"(c0),"f"(c1),"f"(c2),"f"(c3))

// ---------------------------------------------------------------------------
// Fused proj + attention. CTA = (bh, qtile of 256 queries), 512 threads.
//   skey (key-major, word idx XOR (key&4)):   [1024][8] u32
//   khiT/kloT (feature-major, stride 516):    [8][516] u32
// Softmax scale folded into A-fragments; weights hi/lo split (3 AV MMAs);
// denominator on the FMA pipe (FADDs + end shuffles) — tensor pipe is the
// binder, so denominators must NOT consume MMA slots (R10 regression).
// ---------------------------------------------------------------------------
#define ATTN_SMEM_BYTES 65792   // (8192 + 4128 + 4128) u32

__global__ __launch_bounds__(512, 2) void attn_fused(const float* __restrict__ x,
                                                     const float* __restrict__ theta) {
    extern __shared__ __align__(16) u32 sm[];
    u32* skey = sm;                 // [1024*8]
    u32* khiT = sm + 8192;          // [8*516]
    u32* kloT = sm + 8192 + 4128;   // [8*516]

    int bh = blockIdx.x;
    int b = bh >> 3, h = bh & 7;
    int qt = blockIdx.y;
    int tid = threadIdx.x;

    float th[8];
#pragma unroll
    for (int i = 0; i < 8; i++) th[i] = __ldg(&theta[i]);

    // ---------------- build phase: keys 2*tid, 2*tid+1 ----------------
    const float* xb = x + (size_t)(b * SS) * 64 + h * 8;
    {
        float hi[2][8], lo[2][8];
#pragma unroll
        for (int j = 0; j < 2; j++) {
            int s = tid * 2 + j;
            const float4* xs = (const float4*)(xb + (size_t)s * 64);
            float4 v0 = xs[0], v1 = xs[1];
            float a[8] = {v0.x, v0.y, v0.z, v0.w, v1.x, v1.y, v1.z, v1.w};
            float c[8];
#pragma unroll
            for (int i = 0; i < 8; i++) c[i] = __cosf(a[i] + th[i]);
            float p[8];
            p[1] = c[0] * c[1];
#pragma unroll
            for (int w = 2; w < 8; w++) p[w] = p[w - 1] * c[w];
            float qq = c[1];
#pragma unroll
            for (int i = 2; i < 8; i++) qq *= c[i];
            p[0] = qq;
#pragma unroll
            for (int i = 0; i < 8; i++) {
                float hf = bfrnd(p[i]);
                hi[j][i] = hf;
                lo[j][i] = p[i] - hf;
            }
            uint4 HW = make_uint4(cvtpk(hi[j][1], hi[j][0]), cvtpk(hi[j][3], hi[j][2]),
                                  cvtpk(hi[j][5], hi[j][4]), cvtpk(hi[j][7], hi[j][6]));
            uint4 LW = make_uint4(cvtpk(lo[j][1], lo[j][0]), cvtpk(lo[j][3], lo[j][2]),
                                  cvtpk(lo[j][5], lo[j][4]), cvtpk(lo[j][7], lo[j][6]));
            uint4* kp = (uint4*)(skey + s * 8);
            if (s & 4) { kp[0] = LW; kp[1] = HW; }   // word index XOR 4
            else       { kp[0] = HW; kp[1] = LW; }
        }
        int pw = tid;
#pragma unroll
        for (int f = 0; f < 8; f++) {
            khiT[f * 516 + pw] = cvtpk(hi[1][f], hi[0][f]);   // low half = even key
            kloT[f * 516 + pw] = cvtpk(lo[1][f], lo[0][f]);
        }
    }
    __syncthreads();

    // ---------------- main loop: warp = 16 queries ----------------
    int lane = tid & 31, warp = tid >> 5;
    int g  = lane >> 2;        // 0..7
    int tc = lane & 3;         // 0..3
    int sw = g & 4;
    int hiOff = tc ^ sw;
    int loOff = hiOff ^ 4;

    int qbase = qt * 256 + warp * 16;
    int q0 = qbase + g;        // q0&4 == g&4
    int q1 = q0 + 8;

    // A-fragments with softmax scale folded in: s = kexp*(qhi+qlo), re-split
    const float kexp = 1.4426950408889634f * 0.35355339059327373f;
    u32 A0, A1, A2, A3;
    {
        u32 h0 = skey[q0 * 8 + hiOff], l0 = skey[q0 * 8 + loOff];
        u32 h1 = skey[q1 * 8 + hiOff], l1 = skey[q1 * 8 + loOff];
        float f0 = (bflo_f(h0) + bflo_f(l0)) * kexp;
        float f1 = (bfhi_f(h0) + bfhi_f(l0)) * kexp;
        float g0 = (bflo_f(h1) + bflo_f(l1)) * kexp;
        float g1 = (bfhi_f(h1) + bfhi_f(l1)) * kexp;
        float f0h = bfrnd(f0), f1h = bfrnd(f1);
        float g0h = bfrnd(g0), g1h = bfrnd(g1);
        A0 = cvtpk(f1h, f0h);
        A1 = cvtpk(g1h, g0h);
        A2 = cvtpk(f1 - f1h, f0 - f0h);
        A3 = cvtpk(g1 - g1h, g0 - g0h);
    }

    float o0 = 0.f, o1 = 0.f, o2 = 0.f, o3 = 0.f;
    float den0 = 0.f, den1 = 0.f;

#pragma unroll 2
    for (int kb = 0; kb < SS; kb += 16) {
        int k1 = kb + g, k2 = kb + 8 + g;   // k&4 == g&4
        u32 bh1 = skey[k1 * 8 + hiOff];
        u32 bl1 = skey[k1 * 8 + loOff];
        u32 bh2 = skey[k2 * 8 + hiOff];
        u32 bl2 = skey[k2 * 8 + loOff];

        // scores (scale folded into A): exact fp32 dot via hi/lo split
        float d10, d11, d12, d13, d20, d21, d22, d23;
        MMA_BF16(d10, d11, d12, d13, A0, A1, A2, A3, bh1, bh1, 0.f, 0.f, 0.f, 0.f);
        MMA_BF16(d10, d11, d12, d13, A0, A1, A2, A3, bl1, bl1, d10, d11, d12, d13);
        MMA_BF16(d20, d21, d22, d23, A0, A1, A2, A3, bh2, bh2, 0.f, 0.f, 0.f, 0.f);
        MMA_BF16(d20, d21, d22, d23, A0, A1, A2, A3, bl2, bl2, d20, d21, d22, d23);

        // softmax weights straight off the MMA output
        float w10 = ex2(d10), w11 = ex2(d11);
        float w12 = ex2(d12), w13 = ex2(d13);
        float w20 = ex2(d20), w21 = ex2(d21);
        float w22 = ex2(d22), w23 = ex2(d23);
        den0 += (w10 + w11) + (w20 + w21);   // row g   (FMA pipe — idle capacity)
        den1 += (w12 + w13) + (w22 + w23);   // row g+8

        u32 W0 = cvtpk(w11, w10);
        u32 W1 = cvtpk(w13, w12);
        u32 W2 = cvtpk(w21, w20);
        u32 W3 = cvtpk(w23, w22);
        u32 L0 = cvtpk(w11 - bfhi_f(W0), w10 - bflo_f(W0));
        u32 L1 = cvtpk(w13 - bfhi_f(W1), w12 - bflo_f(W1));
        u32 L2 = cvtpk(w21 - bfhi_f(W2), w20 - bflo_f(W2));
        u32 L3 = cvtpk(w23 - bfhi_f(W3), w22 - bflo_f(W3));

        int cw = kb >> 1;
        u32 Bh0 = khiT[g * 516 + cw + tc];
        u32 Bh1 = khiT[g * 516 + cw + 4 + tc];
        u32 Bl0 = kloT[g * 516 + cw + tc];
        u32 Bl1 = kloT[g * 516 + cw + 4 + tc];

        MMA_BF16(o0, o1, o2, o3, W0, W1, W2, W3, Bh0, Bh1, o0, o1, o2, o3);
        MMA_BF16(o0, o1, o2, o3, W0, W1, W2, W3, Bl0, Bl1, o0, o1, o2, o3);
        MMA_BF16(o0, o1, o2, o3, L0, L1, L2, L3, Bh0, Bh1, o0, o1, o2, o3);
    }

    // full denominators: reduce over the quad (same g)
    den0 += __shfl_xor_sync(0xffffffffu, den0, 1);
    den0 += __shfl_xor_sync(0xffffffffu, den0, 2);
    den1 += __shfl_xor_sync(0xffffffffu, den1, 1);
    den1 += __shfl_xor_sync(0xffffffffu, den1, 2);
    float i0 = __frcp_rn(den0), i1 = __frcp_rn(den1);

    int tok0 = b * SS + q0;
    int tok1 = tok0 + 8;
    float2* o2p = (float2*)g_attn;
    o2p[tok0 * 32 + h * 4 + tc] = make_float2(o0 * i0, o1 * i0);
    o2p[tok1 * 32 + h * 4 + tc] = make_float2(o2 * i1, o3 * i1);
}

// ---------------------------------------------------------------------------
// Kernel 3: out[token, e] = sum_k attn[token, k] * W[e, k]
// 1024 CTAs x 128 thr x 8 tokens; thread = 1 token x 4 outputs.
// 2x the warps of the 2-token tiling (6.9/SMSP) to hide LDS/latency;
// W fill stays 8 parallel LDG.128 per thread.
// ---------------------------------------------------------------------------
__global__ __launch_bounds__(128) void combine_kernel(const float* __restrict__ W,
                                                      float* __restrict__ out) {
    __shared__ float wt[EE * 68];        // wt[k*68+e] = W[e*64+k], padded rows
    __shared__ float rows[8][68];        // 8 token rows, padded

    int tid = threadIdx.x;

    // W fill: 1024 float4 reads, 8 per thread, all independent
    const float4* W4 = (const float4*)W;
    float4 v[8];
#pragma unroll
    for (int j = 0; j < 8; j++) v[j] = W4[tid + j * 128];
#pragma unroll
    for (int j = 0; j < 8; j++) {
        int idx = tid + j * 128;          // e = idx>>4, k0 = (idx&15)*4
        int e = idx >> 4, k0 = (idx & 15) * 4;
        wt[(k0 + 0) * 68 + e] = v[j].x;
        wt[(k0 + 1) * 68 + e] = v[j].y;
        wt[(k0 + 2) * 68 + e] = v[j].z;
        wt[(k0 + 3) * 68 + e] = v[j].w;
    }

    // token rows: 8 tokens x 16 float4 = 128, 1 per thread
    int token0 = blockIdx.x * 8;
    const float4* ga4 = (const float4*)g_attn + token0 * 16;
    {
        int t = tid >> 4, kg = tid & 15;
        float4 vv = ga4[tid];
        rows[t][kg * 4 + 0] = vv.x; rows[t][kg * 4 + 1] = vv.y;
        rows[t][kg * 4 + 2] = vv.z; rows[t][kg * 4 + 3] = vv.w;
    }
    __syncthreads();

    int t  = tid >> 4;      // token 0..7
    int og = tid & 15;      // e-quad: outputs og*4 .. og*4+3
    const ulonglong2* wt2 = (const ulonglong2*)wt;   // 17 units per row

    u64 a0 = 0, a1 = 0;
#pragma unroll
    for (int k = 0; k < EE; k++) {
        ulonglong2 bw = wt2[k * 17 + og];
        float r = rows[t][k];
        u64 rr = pk2(r, r);
        a0 = pfma(rr, bw.x, a0);
        a1 = pfma(rr, bw.y, a1);
    }
    ulonglong2* o2 = (ulonglong2*)out;
    ulonglong2 r0; r0.x = a0; r0.y = a1;
    o2[(token0 + t) * 16 + og] = r0;
}

// ---------------------------------------------------------------------------
extern "C" void kernel_launch(void* const* d_in, const int* in_sizes, int n_in,
                              void* d_out, int out_size) {
    const float* x      = (const float*)d_in[0];   // [8,1024,64]
    const float* theta  = (const float*)d_in[1];   // [8]
    const float* Wc     = (const float*)d_in[2];   // [64,64]
    float* out          = (float*)d_out;           // [8,1024,64]

    cudaFuncSetAttribute(attn_fused, cudaFuncAttributeMaxDynamicSharedMemorySize,
                         ATTN_SMEM_BYTES);

    dim3 agrid(NBH, SS / 256);
    attn_fused<<<agrid, 512, ATTN_SMEM_BYTES>>>(x, theta);

    combine_kernel<<<NTOK / 8, 128>>>(Wc, out);
}

// round 12
// speedup vs baseline: 1.2388x; 1.2388x over previous
#include <cuda_runtime.h>
#include <cuda_bf16.h>

#define BB 8
#define SS 1024
#define HH 8
#define EE 64
#define NBH (BB*HH)
#define NTOK (BB*SS)

typedef unsigned long long u64;
typedef unsigned int u32;

__device__ __align__(16) float g_attn[NTOK * EE];   // 2 MB scratch

// ---------------------------------------------------------------------------
// helpers
// ---------------------------------------------------------------------------
__device__ __forceinline__ u64 pk2(float lo, float hi) {
    u64 r; asm("mov.b64 %0, {%1, %2};" : "=l"(r) : "f"(lo), "f"(hi)); return r;
}
__device__ __forceinline__ u64 pfma(u64 a, u64 b, u64 c) {
    u64 d; asm("fma.rn.f32x2 %0, %1, %2, %3;" : "=l"(d) : "l"(a), "l"(b), "l"(c)); return d;
}
__device__ __forceinline__ u64 padd64(u64 a, u64 b) {
    u64 d; asm("add.rn.f32x2 %0, %1, %2;" : "=l"(d) : "l"(a), "l"(b)); return d;
}
__device__ __forceinline__ float ex2(float x) {
    float y; asm("ex2.approx.f32 %0, %1;" : "=f"(y) : "f"(x)); return y;
}
// pack two fp32 -> bf16x2; first arg lands in HIGH half, second in LOW half
__device__ __forceinline__ u32 cvtpk(float hi, float lo) {
    u32 r; asm("cvt.rn.bf16x2.f32 %0, %1, %2;" : "=r"(r) : "f"(hi), "f"(lo)); return r;
}
// bf16x2 halves back to fp32 (bf16->f32 is a 16-bit shift)
__device__ __forceinline__ float bflo_f(u32 w) { return __uint_as_float(w << 16); }
__device__ __forceinline__ float bfhi_f(u32 w) { return __uint_as_float(w & 0xffff0000u); }
__device__ __forceinline__ float bfrnd(float v) {
    return __bfloat162float(__float2bfloat16(v));
}

// m16n8k16 row.col bf16 MMA, fp32 accum (HMMA fallback path, sm_80+ PTX)
#define MMA_BF16(d0,d1,d2,d3, a0,a1,a2,a3, b0,b1, c0,c1,c2,c3) \
  asm volatile("mma.sync.aligned.m16n8k16.row.col.f32.bf16.bf16.f32 " \
    "{%0,%1,%2,%3}, {%4,%5,%6,%7}, {%8,%9}, {%10,%11,%12,%13};" \
    : "=f"(d0),"=f"(d1),"=f"(d2),"=f"(d3) \
    : "r"(a0),"r"(a1),"r"(a2),"r"(a3), "r"(b0),"r"(b1), \
      "f"(c0),"f"(c1),"f"(c2),"f"(c3))

// ---------------------------------------------------------------------------
// Fused proj + attention. CTA = (bh, qtile of 256 queries), 512 threads.
//   skey (key-major, word idx XOR (key&4)):   [1024][8] u32
//   khiT/kloT (feature-major, stride 516):    [8][516] u32
// 6 MMAs/iter: 4 score (exact fp32 split) + 2 AV (bf16 weights x exact k).
// Denominator = sum of the SAME bf16-rounded weights -> output is an exactly
// convex combination under w_hat = bf16(w); systematic rounding cancels.
// ---------------------------------------------------------------------------
#define ATTN_SMEM_BYTES 65792   // (8192 + 4128 + 4128) u32

__global__ __launch_bounds__(512, 2) void attn_fused(const float* __restrict__ x,
                                                     const float* __restrict__ theta) {
    extern __shared__ __align__(16) u32 sm[];
    u32* skey = sm;                 // [1024*8]
    u32* khiT = sm + 8192;          // [8*516]
    u32* kloT = sm + 8192 + 4128;   // [8*516]

    int bh = blockIdx.x;
    int b = bh >> 3, h = bh & 7;
    int qt = blockIdx.y;
    int tid = threadIdx.x;

    float th[8];
#pragma unroll
    for (int i = 0; i < 8; i++) th[i] = __ldg(&theta[i]);

    // ---------------- build phase: keys 2*tid, 2*tid+1 ----------------
    const float* xb = x + (size_t)(b * SS) * 64 + h * 8;
    {
        float hi[2][8], lo[2][8];
#pragma unroll
        for (int j = 0; j < 2; j++) {
            int s = tid * 2 + j;
            const float4* xs = (const float4*)(xb + (size_t)s * 64);
            float4 v0 = xs[0], v1 = xs[1];
            float a[8] = {v0.x, v0.y, v0.z, v0.w, v1.x, v1.y, v1.z, v1.w};
            float c[8];
#pragma unroll
            for (int i = 0; i < 8; i++) c[i] = __cosf(a[i] + th[i]);
            float p[8];
            p[1] = c[0] * c[1];
#pragma unroll
            for (int w = 2; w < 8; w++) p[w] = p[w - 1] * c[w];
            float qq = c[1];
#pragma unroll
            for (int i = 2; i < 8; i++) qq *= c[i];
            p[0] = qq;
#pragma unroll
            for (int i = 0; i < 8; i++) {
                float hf = bfrnd(p[i]);
                hi[j][i] = hf;
                lo[j][i] = p[i] - hf;
            }
            uint4 HW = make_uint4(cvtpk(hi[j][1], hi[j][0]), cvtpk(hi[j][3], hi[j][2]),
                                  cvtpk(hi[j][5], hi[j][4]), cvtpk(hi[j][7], hi[j][6]));
            uint4 LW = make_uint4(cvtpk(lo[j][1], lo[j][0]), cvtpk(lo[j][3], lo[j][2]),
                                  cvtpk(lo[j][5], lo[j][4]), cvtpk(lo[j][7], lo[j][6]));
            uint4* kp = (uint4*)(skey + s * 8);
            if (s & 4) { kp[0] = LW; kp[1] = HW; }   // word index XOR 4
            else       { kp[0] = HW; kp[1] = LW; }
        }
        int pw = tid;
#pragma unroll
        for (int f = 0; f < 8; f++) {
            khiT[f * 516 + pw] = cvtpk(hi[1][f], hi[0][f]);   // low half = even key
            kloT[f * 516 + pw] = cvtpk(lo[1][f], lo[0][f]);
        }
    }
    __syncthreads();

    // ---------------- main loop: warp = 16 queries ----------------
    int lane = tid & 31, warp = tid >> 5;
    int g  = lane >> 2;        // 0..7
    int tc = lane & 3;         // 0..3
    int sw = g & 4;
    int hiOff = tc ^ sw;
    int loOff = hiOff ^ 4;

    int qbase = qt * 256 + warp * 16;
    int q0 = qbase + g;        // q0&4 == g&4
    int q1 = q0 + 8;

    // A-fragments with softmax scale folded in: s = kexp*(qhi+qlo), re-split
    const float kexp = 1.4426950408889634f * 0.35355339059327373f;
    u32 A0, A1, A2, A3;
    {
        u32 h0 = skey[q0 * 8 + hiOff], l0 = skey[q0 * 8 + loOff];
        u32 h1 = skey[q1 * 8 + hiOff], l1 = skey[q1 * 8 + loOff];
        float f0 = (bflo_f(h0) + bflo_f(l0)) * kexp;
        float f1 = (bfhi_f(h0) + bfhi_f(l0)) * kexp;
        float g0 = (bflo_f(h1) + bflo_f(l1)) * kexp;
        float g1 = (bfhi_f(h1) + bfhi_f(l1)) * kexp;
        float f0h = bfrnd(f0), f1h = bfrnd(f1);
        float g0h = bfrnd(g0), g1h = bfrnd(g1);
        A0 = cvtpk(f1h, f0h);
        A1 = cvtpk(g1h, g0h);
        A2 = cvtpk(f1 - f1h, f0 - f0h);
        A3 = cvtpk(g1 - g1h, g0 - g0h);
    }

    float o0 = 0.f, o1 = 0.f, o2 = 0.f, o3 = 0.f;
    float den0 = 0.f, den1 = 0.f;

#pragma unroll 2
    for (int kb = 0; kb < SS; kb += 16) {
        int k1 = kb + g, k2 = kb + 8 + g;   // k&4 == g&4
        u32 bh1 = skey[k1 * 8 + hiOff];
        u32 bl1 = skey[k1 * 8 + loOff];
        u32 bh2 = skey[k2 * 8 + hiOff];
        u32 bl2 = skey[k2 * 8 + loOff];

        // scores (scale folded into A): exact fp32 dot via hi/lo split
        float d10, d11, d12, d13, d20, d21, d22, d23;
        MMA_BF16(d10, d11, d12, d13, A0, A1, A2, A3, bh1, bh1, 0.f, 0.f, 0.f, 0.f);
        MMA_BF16(d10, d11, d12, d13, A0, A1, A2, A3, bl1, bl1, d10, d11, d12, d13);
        MMA_BF16(d20, d21, d22, d23, A0, A1, A2, A3, bh2, bh2, 0.f, 0.f, 0.f, 0.f);
        MMA_BF16(d20, d21, d22, d23, A0, A1, A2, A3, bl2, bl2, d20, d21, d22, d23);

        // softmax weights straight off the MMA output
        float w10 = ex2(d10), w11 = ex2(d11);
        float w12 = ex2(d12), w13 = ex2(d13);
        float w20 = ex2(d20), w21 = ex2(d21);
        float w22 = ex2(d22), w23 = ex2(d23);

        u32 W0 = cvtpk(w11, w10);
        u32 W1 = cvtpk(w13, w12);
        u32 W2 = cvtpk(w21, w20);
        u32 W3 = cvtpk(w23, w22);

        // denominator from the SAME bf16-rounded weights (convex combination)
        den0 += (bflo_f(W0) + bfhi_f(W0)) + (bflo_f(W2) + bfhi_f(W2));  // row g
        den1 += (bflo_f(W1) + bfhi_f(W1)) + (bflo_f(W3) + bfhi_f(W3));  // row g+8

        int cw = kb >> 1;
        u32 Bh0 = khiT[g * 516 + cw + tc];
        u32 Bh1 = khiT[g * 516 + cw + 4 + tc];
        u32 Bl0 = kloT[g * 516 + cw + tc];
        u32 Bl1 = kloT[g * 516 + cw + 4 + tc];

        MMA_BF16(o0, o1, o2, o3, W0, W1, W2, W3, Bh0, Bh1, o0, o1, o2, o3);
        MMA_BF16(o0, o1, o2, o3, W0, W1, W2, W3, Bl0, Bl1, o0, o1, o2, o3);
    }

    // full denominators: reduce over the quad (same g)
    den0 += __shfl_xor_sync(0xffffffffu, den0, 1);
    den0 += __shfl_xor_sync(0xffffffffu, den0, 2);
    den1 += __shfl_xor_sync(0xffffffffu, den1, 1);
    den1 += __shfl_xor_sync(0xffffffffu, den1, 2);
    float i0 = __frcp_rn(den0), i1 = __frcp_rn(den1);

    int tok0 = b * SS + q0;
    int tok1 = tok0 + 8;
    float2* o2p = (float2*)g_attn;
    o2p[tok0 * 32 + h * 4 + tc] = make_float2(o0 * i0, o1 * i0);
    o2p[tok1 * 32 + h * 4 + tc] = make_float2(o2 * i1, o3 * i1);
}

// ---------------------------------------------------------------------------
// Kernel 3: out[token, e] = sum_k attn[token, k] * W[e, k]
// 512 CTAs x 256 thr, 16 tokens/CTA, split-k:
//   thread = (kh, token-pair, e-quad); each does 32 k-iters, wt LDS.128
//   reused across 2 tokens (R10 traffic) but 2x warps (6.9/SMSP) to hide
//   latency. kh halves reduced via 4KB smem.
// ---------------------------------------------------------------------------
__global__ __launch_bounds__(256) void combine_kernel(const float* __restrict__ W,
                                                      float* __restrict__ out) {
    __shared__ float wt[EE * 68];        // wt[k*68+e] = W[e*64+k], padded rows
    __shared__ float rows[16][68];       // 16 token rows, padded
    __shared__ u64 red[128 * 4];         // kh=1 partials

    int tid = threadIdx.x;

    // W fill: 1024 float4 reads, 4 per thread, all independent
    const float4* W4 = (const float4*)W;
    float4 v[4];
#pragma unroll
    for (int j = 0; j < 4; j++) v[j] = W4[tid + j * 256];
#pragma unroll
    for (int j = 0; j < 4; j++) {
        int idx = tid + j * 256;          // e = idx>>4, k0 = (idx&15)*4
        int e = idx >> 4, k0 = (idx & 15) * 4;
        wt[(k0 + 0) * 68 + e] = v[j].x;
        wt[(k0 + 1) * 68 + e] = v[j].y;
        wt[(k0 + 2) * 68 + e] = v[j].z;
        wt[(k0 + 3) * 68 + e] = v[j].w;
    }

    // token rows: 16 tokens x 16 float4 = 256, 1 per thread
    int token0 = blockIdx.x * 16;
    const float4* ga4 = (const float4*)g_attn + token0 * 16;
    {
        int t = tid >> 4, kg = tid & 15;
        float4 vv = ga4[tid];
        rows[t][kg * 4 + 0] = vv.x; rows[t][kg * 4 + 1] = vv.y;
        rows[t][kg * 4 + 2] = vv.z; rows[t][kg * 4 + 3] = vv.w;
    }
    __syncthreads();

    int og = tid & 15;            // e-quad: outputs og*4 .. og*4+3
    int tp = (tid >> 4) & 7;      // token pair -> tokens 2tp, 2tp+1
    int kh = tid >> 7;            // k half: 0 or 1
    int kb = kh * 32;
    const ulonglong2* wt2 = (const ulonglong2*)wt;   // 17 units per row

    u64 a0 = 0, a1 = 0, c0 = 0, c1 = 0;
#pragma unroll
    for (int kk = 0; kk < 32; kk++) {
        int k = kb + kk;
        ulonglong2 bw = wt2[k * 17 + og];
        float r0 = rows[2 * tp + 0][k];
        float r1 = rows[2 * tp + 1][k];
        u64 rr0 = pk2(r0, r0);
        u64 rr1 = pk2(r1, r1);
        a0 = pfma(rr0, bw.x, a0);
        a1 = pfma(rr0, bw.y, a1);
        c0 = pfma(rr1, bw.x, c0);
        c1 = pfma(rr1, bw.y, c1);
    }

    int slot = tid & 127;
    if (kh == 1) {
        red[slot * 4 + 0] = a0; red[slot * 4 + 1] = a1;
        red[slot * 4 + 2] = c0; red[slot * 4 + 3] = c1;
    }
    __syncthreads();
    if (kh == 0) {
        a0 = padd64(a0, red[slot * 4 + 0]);
        a1 = padd64(a1, red[slot * 4 + 1]);
        c0 = padd64(c0, red[slot * 4 + 2]);
        c1 = padd64(c1, red[slot * 4 + 3]);
        ulonglong2* o2 = (ulonglong2*)out;
        int t0 = token0 + 2 * tp;
        ulonglong2 r0; r0.x = a0; r0.y = a1;
        ulonglong2 r1; r1.x = c0; r1.y = c1;
        o2[(t0 + 0) * 16 + og] = r0;
        o2[(t0 + 1) * 16 + og] = r1;
    }
}

// ---------------------------------------------------------------------------
extern "C" void kernel_launch(void* const* d_in, const int* in_sizes, int n_in,
                              void* d_out, int out_size) {
    const float* x      = (const float*)d_in[0];   // [8,1024,64]
    const float* theta  = (const float*)d_in[1];   // [8]
    const float* Wc     = (const float*)d_in[2];   // [64,64]
    float* out          = (float*)d_out;           // [8,1024,64]

    cudaFuncSetAttribute(attn_fused, cudaFuncAttributeMaxDynamicSharedMemorySize,
                         ATTN_SMEM_BYTES);

    dim3 agrid(NBH, SS / 256);
    attn_fused<<<agrid, 512, ATTN_SMEM_BYTES>>>(x, theta);

    combine_kernel<<<NTOK / 16, 256>>>(Wc, out);
}

// round 13
// speedup vs baseline: 1.2508x; 1.0097x over previous
#include <cuda_runtime.h>
#include <cuda_bf16.h>

#define BB 8
#define SS 1024
#define HH 8
#define EE 64
#define NBH (BB*HH)
#define NTOK (BB*SS)

typedef unsigned long long u64;
typedef unsigned int u32;

__device__ __align__(16) float g_attn[NTOK * EE];   // 2 MB scratch

// ---------------------------------------------------------------------------
// helpers
// ---------------------------------------------------------------------------
__device__ __forceinline__ u64 pk2(float lo, float hi) {
    u64 r; asm("mov.b64 %0, {%1, %2};" : "=l"(r) : "f"(lo), "f"(hi)); return r;
}
__device__ __forceinline__ u64 pfma(u64 a, u64 b, u64 c) {
    u64 d; asm("fma.rn.f32x2 %0, %1, %2, %3;" : "=l"(d) : "l"(a), "l"(b), "l"(c)); return d;
}
__device__ __forceinline__ float ex2(float x) {
    float y; asm("ex2.approx.f32 %0, %1;" : "=f"(y) : "f"(x)); return y;
}
// round fp32 -> tf32 (rna, unbiased); result bits are fp32-compatible
__device__ __forceinline__ u32 cvt_tf32(float f) {
    u32 r; asm("cvt.rna.tf32.f32 %0, %1;" : "=r"(r) : "f"(f)); return r;
}

// m16n8k8 row.col tf32 MMA, fp32 accum (sm_80+ PTX, HMMA fallback)
#define MMA_TF32(d0,d1,d2,d3, a0,a1,a2,a3, b0,b1, c0,c1,c2,c3) \
  asm volatile("mma.sync.aligned.m16n8k8.row.col.f32.tf32.tf32.f32 " \
    "{%0,%1,%2,%3}, {%4,%5,%6,%7}, {%8,%9}, {%10,%11,%12,%13};" \
    : "=f"(d0),"=f"(d1),"=f"(d2),"=f"(d3) \
    : "r"(a0),"r"(a1),"r"(a2),"r"(a3), "r"(b0),"r"(b1), \
      "f"(c0),"f"(c1),"f"(c2),"f"(c3))

// ---------------------------------------------------------------------------
// Fused proj + attention, all-tf32 datapath. CTA = (bh, qtile 256), 512 thr.
// skf[1024][12]: tf32-pre-rounded key plane, stride 12 -> ALL main-loop
// LDS patterns conflict-free. 4 MMAs per 16 keys:
//   2 score MMAs (q,k tf32; q pre-scaled by log2e/sqrt8)
//   2 AV MMAs (weights tf32-rounded; V = same pre-rounded keys)
// AV avkey permutation: avkey tc := key kb+2tc, avkey tc+4 := key kb+2tc+1,
// so the score D-fragment IS the AV A-fragment (order a0,a1,a2,a3 =
// w[d0], w[d2], w[d1], w[d3]) with V rows loaded in permuted order.
// Denominator = sum of SAME tf32 weights (exactly convex combination).
// ---------------------------------------------------------------------------
#define KSTRIDE 12
#define ATTN_SMEM_BYTES (SS * KSTRIDE * 4)   // 49152

__global__ __launch_bounds__(512, 2) void attn_fused(const float* __restrict__ x,
                                                     const float* __restrict__ theta) {
    extern __shared__ __align__(16) float skf[];   // [1024][12]

    int bh = blockIdx.x;
    int b = bh >> 3, h = bh & 7;
    int qt = blockIdx.y;
    int tid = threadIdx.x;

    float th[8];
#pragma unroll
    for (int i = 0; i < 8; i++) th[i] = __ldg(&theta[i]);

    // ---------------- build phase: keys 2*tid, 2*tid+1 ----------------
    const float* xb = x + (size_t)(b * SS) * 64 + h * 8;
#pragma unroll
    for (int j = 0; j < 2; j++) {
        int s = tid * 2 + j;
        const float4* xs = (const float4*)(xb + (size_t)s * 64);
        float4 v0 = xs[0], v1 = xs[1];
        float a[8] = {v0.x, v0.y, v0.z, v0.w, v1.x, v1.y, v1.z, v1.w};
        float c[8];
#pragma unroll
        for (int i = 0; i < 8; i++) c[i] = __cosf(a[i] + th[i]);
        float p[8];
        p[1] = c[0] * c[1];
#pragma unroll
        for (int w = 2; w < 8; w++) p[w] = p[w - 1] * c[w];
        float qq = c[1];
#pragma unroll
        for (int i = 2; i < 8; i++) qq *= c[i];
        p[0] = qq;
        // pre-round to tf32 (rna) so MMA truncation is exact & unbiased
        uint4 w0, w1;
        w0.x = cvt_tf32(p[0]); w0.y = cvt_tf32(p[1]);
        w0.z = cvt_tf32(p[2]); w0.w = cvt_tf32(p[3]);
        w1.x = cvt_tf32(p[4]); w1.y = cvt_tf32(p[5]);
        w1.z = cvt_tf32(p[6]); w1.w = cvt_tf32(p[7]);
        uint4* dst = (uint4*)(skf + s * KSTRIDE);   // s*48B, 16B-aligned
        dst[0] = w0; dst[1] = w1;
    }
    __syncthreads();

    // ---------------- main loop: warp = 16 queries ----------------
    int lane = tid & 31, warp = tid >> 5;
    int g  = lane >> 2;        // 0..7
    int tc = lane & 3;         // 0..3

    int qbase = qt * 256 + warp * 16;
    int q0 = qbase + g;
    int q1 = q0 + 8;

    // A-fragment: q values (pre-rounded), softmax scale folded, re-round
    const float kexp = 1.4426950408889634f * 0.35355339059327373f;
    u32 A0 = cvt_tf32(skf[q0 * KSTRIDE + tc]     * kexp);
    u32 A1 = cvt_tf32(skf[q1 * KSTRIDE + tc]     * kexp);
    u32 A2 = cvt_tf32(skf[q0 * KSTRIDE + tc + 4] * kexp);
    u32 A3 = cvt_tf32(skf[q1 * KSTRIDE + tc + 4] * kexp);

    float o0 = 0.f, o1 = 0.f, o2 = 0.f, o3 = 0.f;
    float den0 = 0.f, den1 = 0.f;
    const u32* sku = (const u32*)skf;

#pragma unroll 2
    for (int kb = 0; kb < SS; kb += 16) {
        // score B fragments: key kb+g (group1), kb+8+g (group2)
        u32 b10 = sku[(kb + g) * KSTRIDE + tc];
        u32 b11 = sku[(kb + g) * KSTRIDE + tc + 4];
        u32 b20 = sku[(kb + 8 + g) * KSTRIDE + tc];
        u32 b21 = sku[(kb + 8 + g) * KSTRIDE + tc + 4];

        float d10, d11, d12, d13, d20, d21, d22, d23;
        MMA_TF32(d10, d11, d12, d13, A0, A1, A2, A3, b10, b11, 0.f, 0.f, 0.f, 0.f);
        MMA_TF32(d20, d21, d22, d23, A0, A1, A2, A3, b20, b21, 0.f, 0.f, 0.f, 0.f);
        // d10 = S[q0][kb+2tc], d11 = S[q0][kb+2tc+1], d12/d13 same for q1

        float w10 = ex2(d10), w11 = ex2(d11);
        float w12 = ex2(d12), w13 = ex2(d13);
        float w20 = ex2(d20), w21 = ex2(d21);
        float w22 = ex2(d22), w23 = ex2(d23);

        // tf32-rounded weights (used by BOTH numerator MMA and denominator)
        u32 W10 = cvt_tf32(w10), W11 = cvt_tf32(w11);
        u32 W12 = cvt_tf32(w12), W13 = cvt_tf32(w13);
        u32 W20 = cvt_tf32(w20), W21 = cvt_tf32(w21);
        u32 W22 = cvt_tf32(w22), W23 = cvt_tf32(w23);

        den0 += (__uint_as_float(W10) + __uint_as_float(W11))
              + (__uint_as_float(W20) + __uint_as_float(W21));
        den1 += (__uint_as_float(W12) + __uint_as_float(W13))
              + (__uint_as_float(W22) + __uint_as_float(W23));

        // AV B: V rows in permuted avkey order (feat g of keys kb+2tc, kb+2tc+1)
        u32 v10 = sku[(kb + 2 * tc) * KSTRIDE + g];
        u32 v11 = sku[(kb + 2 * tc + 1) * KSTRIDE + g];
        u32 v20 = sku[(kb + 8 + 2 * tc) * KSTRIDE + g];
        u32 v21 = sku[(kb + 8 + 2 * tc + 1) * KSTRIDE + g];

        // A-fragment of AV = permuted score-D weights: {w[d0], w[d2], w[d1], w[d3]}
        MMA_TF32(o0, o1, o2, o3, W10, W12, W11, W13, v10, v11, o0, o1, o2, o3);
        MMA_TF32(o0, o1, o2, o3, W20, W22, W21, W23, v20, v21, o0, o1, o2, o3);
    }

    // full denominators: reduce over the quad (same g)
    den0 += __shfl_xor_sync(0xffffffffu, den0, 1);
    den0 += __shfl_xor_sync(0xffffffffu, den0, 2);
    den1 += __shfl_xor_sync(0xffffffffu, den1, 1);
    den1 += __shfl_xor_sync(0xffffffffu, den1, 2);
    float i0 = __frcp_rn(den0), i1 = __frcp_rn(den1);

    // o0/o1 = feats 2tc,2tc+1 of q0; o2/o3 = same of q1
    int tok0 = b * SS + q0;
    int tok1 = tok0 + 8;
    float2* o2p = (float2*)g_attn;
    o2p[tok0 * 32 + h * 4 + tc] = make_float2(o0 * i0, o1 * i0);
    o2p[tok1 * 32 + h * 4 + tc] = make_float2(o2 * i1, o3 * i1);
}

// ---------------------------------------------------------------------------
// Kernel 3: out[token, e] = sum_k attn[token, k] * W[e, k]  (R10 version,
// measured best: 512 CTAs x 128 thr, 16 tokens, thread = token-pair x e-quad;
// parallel W fill (MLP=8), wt LDS.128 reused across 2 tokens)
// ---------------------------------------------------------------------------
__global__ __launch_bounds__(128) void combine_kernel(const float* __restrict__ W,
                                                      float* __restrict__ out) {
    __shared__ float wt[EE * 68];        // wt[k*68+e] = W[e*64+k], padded rows
    __shared__ float rows[16][68];       // 16 token rows, padded

    int tid = threadIdx.x;

    const float4* W4 = (const float4*)W;
    float4 v[8];
#pragma unroll
    for (int j = 0; j < 8; j++) v[j] = W4[tid + j * 128];
#pragma unroll
    for (int j = 0; j < 8; j++) {
        int idx = tid + j * 128;
        int e = idx >> 4, k0 = (idx & 15) * 4;
        wt[(k0 + 0) * 68 + e] = v[j].x;
        wt[(k0 + 1) * 68 + e] = v[j].y;
        wt[(k0 + 2) * 68 + e] = v[j].z;
        wt[(k0 + 3) * 68 + e] = v[j].w;
    }

    int token0 = blockIdx.x * 16;
    const float4* ga4 = (const float4*)g_attn + token0 * 16;
#pragma unroll
    for (int j = 0; j < 2; j++) {
        int i = tid + j * 128;
        int t = i >> 4, kg = i & 15;
        float4 vv = ga4[i];
        rows[t][kg * 4 + 0] = vv.x; rows[t][kg * 4 + 1] = vv.y;
        rows[t][kg * 4 + 2] = vv.z; rows[t][kg * 4 + 3] = vv.w;
    }
    __syncthreads();

    int tp = tid >> 4;      // token pair 0..7 -> tokens 2tp, 2tp+1
    int og = tid & 15;      // e-quad: outputs og*4 .. og*4+3
    const ulonglong2* wt2 = (const ulonglong2*)wt;   // 17 units per row

    u64 a0 = 0, a1 = 0, c0 = 0, c1 = 0;
#pragma unroll
    for (int k = 0; k < EE; k++) {
        ulonglong2 bw = wt2[k * 17 + og];
        float r0 = rows[2 * tp + 0][k];
        float r1 = rows[2 * tp + 1][k];
        u64 rr0 = pk2(r0, r0);
        u64 rr1 = pk2(r1, r1);
        a0 = pfma(rr0, bw.x, a0);
        a1 = pfma(rr0, bw.y, a1);
        c0 = pfma(rr1, bw.x, c0);
        c1 = pfma(rr1, bw.y, c1);
    }
    ulonglong2* o2 = (ulonglong2*)out;
    int t0 = token0 + 2 * tp;
    ulonglong2 r0; r0.x = a0; r0.y = a1;
    ulonglong2 r1; r1.x = c0; r1.y = c1;
    o2[(t0 + 0) * 16 + og] = r0;
    o2[(t0 + 1) * 16 + og] = r1;
}

// ---------------------------------------------------------------------------
extern "C" void kernel_launch(void* const* d_in, const int* in_sizes, int n_in,
                              void* d_out, int out_size) {
    const float* x      = (const float*)d_in[0];   // [8,1024,64]
    const float* theta  = (const float*)d_in[1];   // [8]
    const float* Wc     = (const float*)d_in[2];   // [64,64]
    float* out          = (float*)d_out;           // [8,1024,64]

    cudaFuncSetAttribute(attn_fused, cudaFuncAttributeMaxDynamicSharedMemorySize,
                         ATTN_SMEM_BYTES);

    dim3 agrid(NBH, SS / 256);
    attn_fused<<<agrid, 512, ATTN_SMEM_BYTES>>>(x, theta);

    combine_kernel<<<NTOK / 16, 128>>>(Wc, out);
}

// round 14
// speedup vs baseline: 1.5778x; 1.2614x over previous
#include <cuda_runtime.h>
#include <cuda_bf16.h>

#define BB 8
#define SS 1024
#define HH 8
#define EE 64
#define NBH (BB*HH)
#define NTOK (BB*SS)

typedef unsigned long long u64;
typedef unsigned int u32;

__device__ __align__(16) float g_attn[NTOK * EE];   // 2 MB scratch

// ---------------------------------------------------------------------------
// helpers
// ---------------------------------------------------------------------------
__device__ __forceinline__ u64 pk2(float lo, float hi) {
    u64 r; asm("mov.b64 %0, {%1, %2};" : "=l"(r) : "f"(lo), "f"(hi)); return r;
}
__device__ __forceinline__ u64 pfma(u64 a, u64 b, u64 c) {
    u64 d; asm("fma.rn.f32x2 %0, %1, %2, %3;" : "=l"(d) : "l"(a), "l"(b), "l"(c)); return d;
}
__device__ __forceinline__ float ex2(float x) {
    float y; asm("ex2.approx.f32 %0, %1;" : "=f"(y) : "f"(x)); return y;
}
// round fp32 -> tf32 (rna); used in build phase only
__device__ __forceinline__ u32 cvt_tf32(float f) {
    u32 r; asm("cvt.rna.tf32.f32 %0, %1;" : "=r"(r) : "f"(f)); return r;
}
// truncate fp32 bits to tf32 precision (LOP3; matches HW MMA truncation)
__device__ __forceinline__ u32 trunc_tf32(float f) {
    return __float_as_uint(f) & 0xffffe000u;
}

// m16n8k8 row.col tf32 MMA, fp32 accum (sm_80+ PTX, HMMA fallback)
#define MMA_TF32(d0,d1,d2,d3, a0,a1,a2,a3, b0,b1, c0,c1,c2,c3) \
  asm volatile("mma.sync.aligned.m16n8k8.row.col.f32.tf32.tf32.f32 " \
    "{%0,%1,%2,%3}, {%4,%5,%6,%7}, {%8,%9}, {%10,%11,%12,%13};" \
    : "=f"(d0),"=f"(d1),"=f"(d2),"=f"(d3) \
    : "r"(a0),"r"(a1),"r"(a2),"r"(a3), "r"(b0),"r"(b1), \
      "f"(c0),"f"(c1),"f"(c2),"f"(c3))

#define ONES_TF32 0x3F800000u

// ---------------------------------------------------------------------------
// Fused proj + attention, all-tf32. CTA = (bh, qtile 256), 512 thr.
// skf[1024][12]: tf32-pre-rounded key plane (stride 12 -> conflict-free).
// 6 MMAs per 16 keys:
//   2 score (q,k tf32; softmax scale folded into q)
//   2 AV    (truncated-tf32 weights x exact pre-rounded keys)
//   2 den   (same weight A-fragments x ones-B -> d0/d2 = full row sums)
// Weights quantized by BIT TRUNCATION (LOP3, not F2FP cvt) — identical to
// what the MMA reads, so numerator/denominator stay exactly consistent.
// ---------------------------------------------------------------------------
#define KSTRIDE 12
#define ATTN_SMEM_BYTES (SS * KSTRIDE * 4)   // 49152

__global__ __launch_bounds__(512, 2) void attn_fused(const float* __restrict__ x,
                                                     const float* __restrict__ theta) {
    extern __shared__ __align__(16) float skf[];   // [1024][12]

    int bh = blockIdx.x;
    int b = bh >> 3, h = bh & 7;
    int qt = blockIdx.y;
    int tid = threadIdx.x;

    float th[8];
#pragma unroll
    for (int i = 0; i < 8; i++) th[i] = __ldg(&theta[i]);

    // ---------------- build phase: keys 2*tid, 2*tid+1 ----------------
    const float* xb = x + (size_t)(b * SS) * 64 + h * 8;
#pragma unroll
    for (int j = 0; j < 2; j++) {
        int s = tid * 2 + j;
        const float4* xs = (const float4*)(xb + (size_t)s * 64);
        float4 v0 = xs[0], v1 = xs[1];
        float a[8] = {v0.x, v0.y, v0.z, v0.w, v1.x, v1.y, v1.z, v1.w};
        float c[8];
#pragma unroll
        for (int i = 0; i < 8; i++) c[i] = __cosf(a[i] + th[i]);
        float p[8];
        p[1] = c[0] * c[1];
#pragma unroll
        for (int w = 2; w < 8; w++) p[w] = p[w - 1] * c[w];
        float qq = c[1];
#pragma unroll
        for (int i = 2; i < 8; i++) qq *= c[i];
        p[0] = qq;
        uint4 w0, w1;
        w0.x = cvt_tf32(p[0]); w0.y = cvt_tf32(p[1]);
        w0.z = cvt_tf32(p[2]); w0.w = cvt_tf32(p[3]);
        w1.x = cvt_tf32(p[4]); w1.y = cvt_tf32(p[5]);
        w1.z = cvt_tf32(p[6]); w1.w = cvt_tf32(p[7]);
        uint4* dst = (uint4*)(skf + s * KSTRIDE);
        dst[0] = w0; dst[1] = w1;
    }
    __syncthreads();

    // ---------------- main loop: warp = 16 queries ----------------
    int lane = tid & 31, warp = tid >> 5;
    int g  = lane >> 2;        // 0..7
    int tc = lane & 3;         // 0..3

    int qbase = qt * 256 + warp * 16;
    int q0 = qbase + g;
    int q1 = q0 + 8;

    const float kexp = 1.4426950408889634f * 0.35355339059327373f;
    u32 A0 = cvt_tf32(skf[q0 * KSTRIDE + tc]     * kexp);
    u32 A1 = cvt_tf32(skf[q1 * KSTRIDE + tc]     * kexp);
    u32 A2 = cvt_tf32(skf[q0 * KSTRIDE + tc + 4] * kexp);
    u32 A3 = cvt_tf32(skf[q1 * KSTRIDE + tc + 4] * kexp);

    float o0 = 0.f, o1 = 0.f, o2 = 0.f, o3 = 0.f;
    float e0 = 0.f, e1 = 0.f, e2 = 0.f, e3 = 0.f;   // den row-sum accum
    const u32* sku = (const u32*)skf;

#pragma unroll 2
    for (int kb = 0; kb < SS; kb += 16) {
        u32 b10 = sku[(kb + g) * KSTRIDE + tc];
        u32 b11 = sku[(kb + g) * KSTRIDE + tc + 4];
        u32 b20 = sku[(kb + 8 + g) * KSTRIDE + tc];
        u32 b21 = sku[(kb + 8 + g) * KSTRIDE + tc + 4];

        float d10, d11, d12, d13, d20, d21, d22, d23;
        MMA_TF32(d10, d11, d12, d13, A0, A1, A2, A3, b10, b11, 0.f, 0.f, 0.f, 0.f);
        MMA_TF32(d20, d21, d22, d23, A0, A1, A2, A3, b20, b21, 0.f, 0.f, 0.f, 0.f);

        float w10 = ex2(d10), w11 = ex2(d11);
        float w12 = ex2(d12), w13 = ex2(d13);
        float w20 = ex2(d20), w21 = ex2(d21);
        float w22 = ex2(d22), w23 = ex2(d23);

        // tf32-truncated weights (LOP3) — consistent for numerator AND den
        u32 W10 = trunc_tf32(w10), W11 = trunc_tf32(w11);
        u32 W12 = trunc_tf32(w12), W13 = trunc_tf32(w13);
        u32 W20 = trunc_tf32(w20), W21 = trunc_tf32(w21);
        u32 W22 = trunc_tf32(w22), W23 = trunc_tf32(w23);

        u32 v10 = sku[(kb + 2 * tc) * KSTRIDE + g];
        u32 v11 = sku[(kb + 2 * tc + 1) * KSTRIDE + g];
        u32 v20 = sku[(kb + 8 + 2 * tc) * KSTRIDE + g];
        u32 v21 = sku[(kb + 8 + 2 * tc + 1) * KSTRIDE + g];

        // numerator (A = permuted score-D weights)
        MMA_TF32(o0, o1, o2, o3, W10, W12, W11, W13, v10, v11, o0, o1, o2, o3);
        MMA_TF32(o0, o1, o2, o3, W20, W22, W21, W23, v20, v21, o0, o1, o2, o3);
        // denominator: same A-fragments vs ones-B -> e0/e2 = full row sums
        MMA_TF32(e0, e1, e2, e3, W10, W12, W11, W13, ONES_TF32, ONES_TF32, e0, e1, e2, e3);
        MMA_TF32(e0, e1, e2, e3, W20, W22, W21, W23, ONES_TF32, ONES_TF32, e0, e1, e2, e3);
    }

    float i0 = __frcp_rn(e0), i1 = __frcp_rn(e2);

    int tok0 = b * SS + q0;
    int tok1 = tok0 + 8;
    float2* o2p = (float2*)g_attn;
    o2p[tok0 * 32 + h * 4 + tc] = make_float2(o0 * i0, o1 * i0);
    o2p[tok1 * 32 + h * 4 + tc] = make_float2(o2 * i1, o3 * i1);
}

// ---------------------------------------------------------------------------
// Kernel 3: out[token, e] = sum_k attn[token, k] * W[e, k]
// 256 CTAs x 256 thr x 32 tokens; thread = token-pair x e-quad (R10 loop).
// W fill amortized over 2x tokens (4 parallel LDG.128/thread).
// ---------------------------------------------------------------------------
__global__ __launch_bounds__(256) void combine_kernel(const float* __restrict__ W,
                                                      float* __restrict__ out) {
    __shared__ float wt[EE * 68];        // wt[k*68+e] = W[e*64+k], padded rows
    __shared__ float rows[32][68];       // 32 token rows, padded

    int tid = threadIdx.x;

    const float4* W4 = (const float4*)W;
    float4 v[4];
#pragma unroll
    for (int j = 0; j < 4; j++) v[j] = W4[tid + j * 256];
#pragma unroll
    for (int j = 0; j < 4; j++) {
        int idx = tid + j * 256;
        int e = idx >> 4, k0 = (idx & 15) * 4;
        wt[(k0 + 0) * 68 + e] = v[j].x;
        wt[(k0 + 1) * 68 + e] = v[j].y;
        wt[(k0 + 2) * 68 + e] = v[j].z;
        wt[(k0 + 3) * 68 + e] = v[j].w;
    }

    int token0 = blockIdx.x * 32;
    const float4* ga4 = (const float4*)g_attn + token0 * 16;
#pragma unroll
    for (int j = 0; j < 2; j++) {
        int i = tid + j * 256;            // 32 tokens x 16 float4 = 512
        int t = i >> 4, kg = i & 15;
        float4 vv = ga4[i];
        rows[t][kg * 4 + 0] = vv.x; rows[t][kg * 4 + 1] = vv.y;
        rows[t][kg * 4 + 2] = vv.z; rows[t][kg * 4 + 3] = vv.w;
    }
    __syncthreads();

    int tp = tid >> 4;      // token pair 0..15 -> tokens 2tp, 2tp+1
    int og = tid & 15;      // e-quad: outputs og*4 .. og*4+3
    const ulonglong2* wt2 = (const ulonglong2*)wt;   // 17 units per row

    u64 a0 = 0, a1 = 0, c0 = 0, c1 = 0;
#pragma unroll
    for (int k = 0; k < EE; k++) {
        ulonglong2 bw = wt2[k * 17 + og];
        float r0 = rows[2 * tp + 0][k];
        float r1 = rows[2 * tp + 1][k];
        u64 rr0 = pk2(r0, r0);
        u64 rr1 = pk2(r1, r1);
        a0 = pfma(rr0, bw.x, a0);
        a1 = pfma(rr0, bw.y, a1);
        c0 = pfma(rr1, bw.x, c0);
        c1 = pfma(rr1, bw.y, c1);
    }
    ulonglong2* o2 = (ulonglong2*)out;
    int t0 = token0 + 2 * tp;
    ulonglong2 r0; r0.x = a0; r0.y = a1;
    ulonglong2 r1; r1.x = c0; r1.y = c1;
    o2[(t0 + 0) * 16 + og] = r0;
    o2[(t0 + 1) * 16 + og] = r1;
}

// ---------------------------------------------------------------------------
extern "C" void kernel_launch(void* const* d_in, const int* in_sizes, int n_in,
                              void* d_out, int out_size) {
    const float* x      = (const float*)d_in[0];   // [8,1024,64]
    const float* theta  = (const float*)d_in[1];   // [8]
    const float* Wc     = (const float*)d_in[2];   // [64,64]
    float* out          = (float*)d_out;           // [8,1024,64]

    cudaFuncSetAttribute(attn_fused, cudaFuncAttributeMaxDynamicSharedMemorySize,
                         ATTN_SMEM_BYTES);

    dim3 agrid(NBH, SS / 256);
    attn_fused<<<agrid, 512, ATTN_SMEM_BYTES>>>(x, theta);

    combine_kernel<<<NTOK / 32, 256>>>(Wc, out);
}